// round 11
// baseline (speedup 1.0000x reference)
#include <cuda_runtime.h>
#include <math_constants.h>

#define NP 512
#define NR 256
#define NS 256

// value-desc, index-asc ordering (matches jax.lax.top_k)
__device__ __forceinline__ bool gt(float v, int i, float w, int j) {
    return (v > w) || ((v == w) && (i < j));
}

// Tie-aware insert into descending triple (a,ai) >= (b,bi) >= (c,ci)
__device__ __forceinline__ void insT(float v, int idx,
                                     float &a, float &b, float &c,
                                     int &ai, int &bi, int &ci) {
    if (gt(v, idx, c, ci)) {
        if (gt(v, idx, b, bi)) {
            c = b; ci = bi;
            if (gt(v, idx, a, ai)) { b = a; bi = ai; a = v; ai = idx; }
            else                   { b = v; bi = idx; }
        } else { c = v; ci = idx; }
    }
}

// Strict-> insert: correct when indices arrive in ascending order
// (equal value never displaces -> lower index wins).
__device__ __forceinline__ void insS(float v, int idx,
                                     float &a, float &b, float &c,
                                     int &ai, int &bi, int &ci) {
    if (v > c) {
        if (v > b) {
            c = b; ci = bi;
            if (v > a) { b = a; bi = ai; a = v; ai = idx; }
            else       { b = v; bi = idx; }
        } else { c = v; ci = idx; }
    }
}

__global__ __launch_bounds__(256) void iapm_kernel(
    const float* __restrict__ score,
    const int*   __restrict__ ref_mask,   // bool stored as 4-byte words
    const int*   __restrict__ src_mask,
    float* __restrict__ out_score,
    float* __restrict__ out_corr)
{
    __shared__ unsigned char smr[NR];
    __shared__ unsigned char sms[NS];

    const int p    = blockIdx.x;
    const int tid  = threadIdx.x;
    const int lane = tid & 31;
    const int warp = tid >> 5;
    const float* base = score + (size_t)p * NR * NS;
    float* os = out_score + (size_t)p * NR * NS;
    float* oc = out_corr  + (size_t)p * NR * NS;

    smr[tid] = (ref_mask[p * NR + tid] != 0) ? 1 : 0;
    sms[tid] = (src_mask[p * NS + tid] != 0) ? 1 : 0;

    // ---- Zero-fill both output slices (full-line float4 stores) ----
    {
        float4 z = make_float4(0.f, 0.f, 0.f, 0.f);
        float4* zs = (float4*)os;
        float4* zc = (float4*)oc;
        #pragma unroll 4
        for (int i = tid; i < NR * NS / 4; i += 256) { zs[i] = z; zc[i] = z; }
    }
    __syncthreads();   // zero-fill visible before any scatter

    // ---- Pass 1: per-row top-3 along s (warp per row); lane0 scatters ----
    for (int rr = warp * 32; rr < warp * 32 + 32; ++rr) {
        const float* row = base + rr * NS;
        float a = -CUDART_INF_F, b = -CUDART_INF_F, c = -CUDART_INF_F;
        int ai = 0x7fffffff, bi = 0x7fffffff, ci = 0x7fffffff;
        // lane owns 8 contiguous elements: two float4 loads, ascending idx
        float4 x0 = ((const float4*)row)[lane * 2];
        float4 x1 = ((const float4*)row)[lane * 2 + 1];
        int ib = lane * 8;
        insS(x0.x, ib + 0, a, b, c, ai, bi, ci);
        insS(x0.y, ib + 1, a, b, c, ai, bi, ci);
        insS(x0.z, ib + 2, a, b, c, ai, bi, ci);
        insS(x0.w, ib + 3, a, b, c, ai, bi, ci);
        insS(x1.x, ib + 4, a, b, c, ai, bi, ci);
        insS(x1.y, ib + 5, a, b, c, ai, bi, ci);
        insS(x1.z, ib + 6, a, b, c, ai, bi, ci);
        insS(x1.w, ib + 7, a, b, c, ai, bi, ci);
        #pragma unroll
        for (int off = 16; off; off >>= 1) {
            float oa = __shfl_down_sync(0xFFFFFFFFu, a, off);
            float ob = __shfl_down_sync(0xFFFFFFFFu, b, off);
            float occ_ = __shfl_down_sync(0xFFFFFFFFu, c, off);
            int  oai = __shfl_down_sync(0xFFFFFFFFu, ai, off);
            int  obi = __shfl_down_sync(0xFFFFFFFFu, bi, off);
            int  oci = __shfl_down_sync(0xFFFFFFFFu, ci, off);
            insT(oa, oai, a, b, c, ai, bi, ci);    // idx mix across lanes:
            insT(ob, obi, a, b, c, ai, bi, ci);    // need explicit tie-break
            insT(occ_, oci, a, b, c, ai, bi, ci);
        }
        if (lane == 0) {
            bool mr = smr[rr] != 0;
            float va = expf(a), vb = expf(b), vc = expf(c);
            os[rr * NS + ai] = 0.5f * va;
            os[rr * NS + bi] = 0.5f * vb;
            os[rr * NS + ci] = 0.5f * vc;
            if (mr) {                       // v=exp(x)>0 always for finite x
                if (sms[ai]) oc[rr * NS + ai] = 1.0f;
                if (sms[bi]) oc[rr * NS + bi] = 1.0f;
                if (sms[ci]) oc[rr * NS + ci] = 1.0f;
            }
        }
    }

    // ---- Pass 2: per-column top-3 along r (thread per column) ----
    float a = -CUDART_INF_F, b = -CUDART_INF_F, c = -CUDART_INF_F;
    int ai = 0x7fffffff, bi = 0x7fffffff, ci = 0x7fffffff;
    #pragma unroll 8
    for (int r = 0; r < NR; ++r)
        insS(base[r * NS + tid], r, a, b, c, ai, bi, ci);  // ascending r

    __syncthreads();   // row scatter complete before column read-modify-write

    // ---- Column scatter (positions unique per thread; RMW adds src half) --
    {
        bool msc = sms[tid] != 0;
        float va = expf(a), vb = expf(b), vc = expf(c);
        int o0 = ai * NS + tid, o1 = bi * NS + tid, o2 = ci * NS + tid;
        os[o0] += 0.5f * va;
        os[o1] += 0.5f * vb;
        os[o2] += 0.5f * vc;
        if (msc) {
            if (smr[ai]) oc[o0] = 1.0f;
            if (smr[bi]) oc[o1] = 1.0f;
            if (smr[ci]) oc[o2] = 1.0f;
        }
    }
}

extern "C" void kernel_launch(void* const* d_in, const int* in_sizes, int n_in,
                              void* d_out, int out_size) {
    // metadata order: matching_score_map [P,R,S] f32, node_corr_scores [P] f32 (unused),
    //                 ref_knn_masks [P,R] bool(4B), src_knn_masks [P,S] bool(4B)
    const float* score = (const float*)d_in[0];
    const int*   refm  = (const int*)d_in[2];
    const int*   srcm  = (const int*)d_in[3];

    float* out = (float*)d_out;
    size_t total = (size_t)NP * NR * NS;
    float* out_corr = out + total;   // [score_map f32 | corr_map bool->f32]

    iapm_kernel<<<NP, 256>>>(score, refm, srcm, out, out_corr);
}

// round 13
// speedup vs baseline: 1.8968x; 1.8968x over previous
#include <cuda_runtime.h>
#include <math_constants.h>

#define NP 512
#define NR 256
#define NS 256
#define CHUNK 32            // rows per K1 block
#define NCH (NR / CHUNK)    // 8 chunks per p-slice

// ---- scratch (no allocations allowed; __device__ globals) ----
__device__ unsigned long long g_rowk[(size_t)NP * NR * 3];        // 3 MB
__device__ unsigned long long g_colp[(size_t)NP * NCH * 3 * NS];  // 25 MB

// Order-preserving 64-bit key: value desc, index asc (jax.lax.top_k order).
__device__ __forceinline__ unsigned long long mk_key(float v, int idx) {
    unsigned u = __float_as_uint(v);
    u = (u & 0x80000000u) ? ~u : (u | 0x80000000u);
    return ((unsigned long long)u << 32) | (unsigned)(~(unsigned)idx);
}
__device__ __forceinline__ int key_idx(unsigned long long k) {
    return (int)(~(unsigned)k);
}
__device__ __forceinline__ float key_val(unsigned long long k) {
    unsigned hi = (unsigned)(k >> 32);
    unsigned orig = (hi & 0x80000000u) ? (hi & 0x7fffffffu) : ~hi;
    return __uint_as_float(orig);
}
// Insert u64 key into descending triple a >= b >= c.
__device__ __forceinline__ void ins3(unsigned long long k,
                                     unsigned long long &a,
                                     unsigned long long &b,
                                     unsigned long long &c) {
    if (k > c) {
        if (k > b) {
            c = b;
            if (k > a) { b = a; a = k; } else { b = k; }
        } else { c = k; }
    }
}
// Strict-> float insert: valid when indices arrive in ascending order.
__device__ __forceinline__ void insS(float v, int idx,
                                     float &a, float &b, float &c,
                                     int &ai, int &bi, int &ci) {
    if (v > c) {
        if (v > b) {
            c = b; ci = bi;
            if (v > a) { b = a; bi = ai; a = v; ai = idx; }
            else       { b = v; bi = idx; }
        } else { c = v; ci = idx; }
    }
}

// ---- K1: per-chunk row top-3 + column-partial top-3, one DRAM read ----
__global__ __launch_bounds__(256) void k_top(const float* __restrict__ score) {
    __shared__ float4 sm4[CHUNK * (NS / 4)];   // 32 KB
    const int tid = threadIdx.x;
    const int p  = blockIdx.x >> 3;
    const int ch = blockIdx.x & 7;
    const int r0 = ch * CHUNK;

    const float4* g4 = (const float4*)(score + ((size_t)p * NR + r0) * NS);
    #pragma unroll
    for (int i = 0; i < (CHUNK * NS / 4) / 256; ++i)   // 8 float4 per thread
        sm4[i * 256 + tid] = g4[i * 256 + tid];
    __syncthreads();
    const float* sm = (const float*)sm4;

    // Row pass: 8-lane group per row -> 4 rows concurrently per warp.
    {
        const int lane = tid & 31, w = tid >> 5;
        const int grp = lane >> 3, x = lane & 7;
        const int rr = w * 4 + grp;                    // local row 0..31
        float a = -CUDART_INF_F, b = -CUDART_INF_F, c = -CUDART_INF_F;
        int ai = 0x7fffffff, bi = 0x7fffffff, ci = 0x7fffffff;
        #pragma unroll
        for (int j = 0; j < 8; ++j) {                  // ascending idx per thread
            float4 v = sm4[rr * (NS / 4) + x + j * 8];
            int ib = (x + j * 8) * 4;
            insS(v.x, ib + 0, a, b, c, ai, bi, ci);
            insS(v.y, ib + 1, a, b, c, ai, bi, ci);
            insS(v.z, ib + 2, a, b, c, ai, bi, ci);
            insS(v.w, ib + 3, a, b, c, ai, bi, ci);
        }
        unsigned long long ka = mk_key(a, ai), kb = mk_key(b, bi), kc = mk_key(c, ci);
        #pragma unroll
        for (int off = 4; off; off >>= 1) {            // merge within 8-lane group
            unsigned long long oa = __shfl_down_sync(0xFFFFFFFFu, ka, off, 8);
            unsigned long long ob = __shfl_down_sync(0xFFFFFFFFu, kb, off, 8);
            unsigned long long oc_ = __shfl_down_sync(0xFFFFFFFFu, kc, off, 8);
            ins3(oa, ka, kb, kc);
            ins3(ob, ka, kb, kc);
            ins3(oc_, ka, kb, kc);
        }
        if (x == 0) {
            size_t o = ((size_t)p * NR + r0 + rr) * 3;
            g_rowk[o + 0] = ka;
            g_rowk[o + 1] = kb;
            g_rowk[o + 2] = kc;
        }
    }

    // Column-partial pass: thread per column over CHUNK rows (smem, conflict-free).
    {
        float a = -CUDART_INF_F, b = -CUDART_INF_F, c = -CUDART_INF_F;
        int ai = 0x7fffffff, bi = 0x7fffffff, ci = 0x7fffffff;
        #pragma unroll
        for (int r = 0; r < CHUNK; ++r)                // ascending global r
            insS(sm[r * NS + tid], r0 + r, a, b, c, ai, bi, ci);
        size_t o = ((size_t)(p * NCH + ch) * 3) * NS + tid;   // [p][ch][k][s]
        g_colp[o + 0 * NS] = mk_key(a, ai);
        g_colp[o + 1 * NS] = mk_key(b, bi);
        g_colp[o + 2 * NS] = mk_key(c, ci);
    }
}

// ---- K2: row scatter (thread per row) ----
__global__ __launch_bounds__(256) void k_rowscat(
    const int* __restrict__ ref_mask, const int* __restrict__ src_mask,
    float* __restrict__ out_score, float* __restrict__ out_corr)
{
    const int p = blockIdx.x, r = threadIdx.x;
    size_t o = ((size_t)p * NR + r) * 3;
    unsigned long long ka = g_rowk[o], kb = g_rowk[o + 1], kc = g_rowk[o + 2];
    int ia = key_idx(ka), ib = key_idx(kb), ic = key_idx(kc);
    float va = expf(key_val(ka)), vb = expf(key_val(kb)), vc = expf(key_val(kc));

    float* os = out_score + ((size_t)p * NR + r) * NS;
    float* oc = out_corr  + ((size_t)p * NR + r) * NS;
    os[ia] = 0.5f * va;
    os[ib] = 0.5f * vb;
    os[ic] = 0.5f * vc;
    if (ref_mask[p * NR + r] != 0) {     // exp(x) > 0 always
        if (src_mask[p * NS + ia] != 0) oc[ia] = 1.0f;
        if (src_mask[p * NS + ib] != 0) oc[ib] = 1.0f;
        if (src_mask[p * NS + ic] != 0) oc[ic] = 1.0f;
    }
}

// ---- K3: column reduce (8 partials) + scatter (thread per column) ----
__global__ __launch_bounds__(256) void k_colscat(
    const int* __restrict__ ref_mask, const int* __restrict__ src_mask,
    float* __restrict__ out_score, float* __restrict__ out_corr)
{
    const int p = blockIdx.x, s = threadIdx.x;
    const unsigned long long* base = g_colp + (size_t)p * NCH * 3 * NS + s;
    unsigned long long a = 0ULL, b = 0ULL, c = 0ULL;
    #pragma unroll
    for (int ch = 0; ch < NCH; ++ch) {
        ins3(base[(ch * 3 + 0) * NS], a, b, c);
        ins3(base[(ch * 3 + 1) * NS], a, b, c);
        ins3(base[(ch * 3 + 2) * NS], a, b, c);
    }
    int ra = key_idx(a), rb = key_idx(b), rc = key_idx(c);
    float va = expf(key_val(a)), vb = expf(key_val(b)), vc = expf(key_val(c));

    float* os = out_score + (size_t)p * NR * NS;
    float* oc = out_corr  + (size_t)p * NR * NS;
    os[ra * NS + s] += 0.5f * va;     // row scatter already done (prior kernel)
    os[rb * NS + s] += 0.5f * vb;
    os[rc * NS + s] += 0.5f * vc;
    if (src_mask[p * NS + s] != 0) {
        if (ref_mask[p * NR + ra] != 0) oc[ra * NS + s] = 1.0f;
        if (ref_mask[p * NR + rb] != 0) oc[rb * NS + s] = 1.0f;
        if (ref_mask[p * NR + rc] != 0) oc[rc * NS + s] = 1.0f;
    }
}

extern "C" void kernel_launch(void* const* d_in, const int* in_sizes, int n_in,
                              void* d_out, int out_size) {
    // inputs: matching_score_map [P,R,S] f32, node_corr_scores [P] f32 (unused),
    //         ref_knn_masks [P,R] bool(4B words), src_knn_masks [P,S] bool(4B words)
    const float* score = (const float*)d_in[0];
    const int*   refm  = (const int*)d_in[2];
    const int*   srcm  = (const int*)d_in[3];

    float* out = (float*)d_out;
    size_t total = (size_t)NP * NR * NS;
    float* out_corr = out + total;    // [score_map f32 | corr_map bool->f32]

    cudaMemsetAsync(d_out, 0, (size_t)out_size * sizeof(float), 0);
    k_top<<<NP * NCH, 256>>>(score);
    k_rowscat<<<NP, 256>>>(refm, srcm, out, out_corr);
    k_colscat<<<NP, 256>>>(refm, srcm, out, out_corr);
}

// round 14
// speedup vs baseline: 2.6105x; 1.3763x over previous
#include <cuda_runtime.h>
#include <math_constants.h>

#define NP 512
#define NR 256
#define NS 256
#define CHUNK 32            // rows per K1/K3 block
#define NCH (NR / CHUNK)    // 8 chunks per p-slice

// ---- scratch (__device__ globals; no allocations allowed) ----
__device__ unsigned long long g_rowk[(size_t)NP * NR * 3];        // 3 MB
__device__ unsigned long long g_colp[(size_t)NP * NCH * 3 * NS];  // 25 MB
__device__ int   g_cidx[(size_t)NP * 3 * NS];                     // col top3 idx (SoA)
__device__ float g_cval[(size_t)NP * 3 * NS];                     // 0.5*exp(val)
__device__ int   g_ridx[(size_t)NP * NR * 3];                     // row top3 idx (AoS)
__device__ float g_rval[(size_t)NP * NR * 3];                     // 0.5*exp(val)

// Order-preserving 64-bit key: value desc, index asc (jax.lax.top_k order).
__device__ __forceinline__ unsigned long long mk_key(float v, int idx) {
    unsigned u = __float_as_uint(v);
    u = (u & 0x80000000u) ? ~u : (u | 0x80000000u);
    return ((unsigned long long)u << 32) | (unsigned)(~(unsigned)idx);
}
__device__ __forceinline__ int key_idx(unsigned long long k) {
    return (int)(~(unsigned)k);
}
__device__ __forceinline__ float key_val(unsigned long long k) {
    unsigned hi = (unsigned)(k >> 32);
    unsigned orig = (hi & 0x80000000u) ? (hi & 0x7fffffffu) : ~hi;
    return __uint_as_float(orig);
}
__device__ __forceinline__ void ins3(unsigned long long k,
                                     unsigned long long &a,
                                     unsigned long long &b,
                                     unsigned long long &c) {
    if (k > c) {
        if (k > b) {
            c = b;
            if (k > a) { b = a; a = k; } else { b = k; }
        } else { c = k; }
    }
}
// Strict-> float insert: valid when indices arrive in ascending order.
__device__ __forceinline__ void insS(float v, int idx,
                                     float &a, float &b, float &c,
                                     int &ai, int &bi, int &ci) {
    if (v > c) {
        if (v > b) {
            c = b; ci = bi;
            if (v > a) { b = a; bi = ai; a = v; ai = idx; }
            else       { b = v; bi = idx; }
        } else { c = v; ci = idx; }
    }
}

// ---- K1: per-chunk row top-3 + column-partial top-3, one DRAM read ----
__global__ __launch_bounds__(256) void k_top(const float* __restrict__ score) {
    __shared__ float4 sm4[CHUNK * (NS / 4)];   // 32 KB
    const int tid = threadIdx.x;
    const int p  = blockIdx.x >> 3;
    const int ch = blockIdx.x & 7;
    const int r0 = ch * CHUNK;

    const float4* g4 = (const float4*)(score + ((size_t)p * NR + r0) * NS);
    #pragma unroll
    for (int i = 0; i < (CHUNK * NS / 4) / 256; ++i)
        sm4[i * 256 + tid] = g4[i * 256 + tid];
    __syncthreads();
    const float* sm = (const float*)sm4;

    // Row pass: 8-lane group per row -> 4 rows concurrently per warp.
    {
        const int lane = tid & 31, w = tid >> 5;
        const int grp = lane >> 3, x = lane & 7;
        const int rr = w * 4 + grp;
        float a = -CUDART_INF_F, b = -CUDART_INF_F, c = -CUDART_INF_F;
        int ai = 0x7fffffff, bi = 0x7fffffff, ci = 0x7fffffff;
        #pragma unroll
        for (int j = 0; j < 8; ++j) {
            float4 v = sm4[rr * (NS / 4) + x + j * 8];
            int ib = (x + j * 8) * 4;
            insS(v.x, ib + 0, a, b, c, ai, bi, ci);
            insS(v.y, ib + 1, a, b, c, ai, bi, ci);
            insS(v.z, ib + 2, a, b, c, ai, bi, ci);
            insS(v.w, ib + 3, a, b, c, ai, bi, ci);
        }
        unsigned long long ka = mk_key(a, ai), kb = mk_key(b, bi), kc = mk_key(c, ci);
        #pragma unroll
        for (int off = 4; off; off >>= 1) {
            unsigned long long oa = __shfl_down_sync(0xFFFFFFFFu, ka, off, 8);
            unsigned long long ob = __shfl_down_sync(0xFFFFFFFFu, kb, off, 8);
            unsigned long long oc_ = __shfl_down_sync(0xFFFFFFFFu, kc, off, 8);
            ins3(oa, ka, kb, kc);
            ins3(ob, ka, kb, kc);
            ins3(oc_, ka, kb, kc);
        }
        if (x == 0) {
            size_t o = ((size_t)p * NR + r0 + rr) * 3;
            g_rowk[o + 0] = ka;
            g_rowk[o + 1] = kb;
            g_rowk[o + 2] = kc;
        }
    }

    // Column-partial pass: thread per column over CHUNK rows.
    {
        float a = -CUDART_INF_F, b = -CUDART_INF_F, c = -CUDART_INF_F;
        int ai = 0x7fffffff, bi = 0x7fffffff, ci = 0x7fffffff;
        #pragma unroll
        for (int r = 0; r < CHUNK; ++r)
            insS(sm[r * NS + tid], r0 + r, a, b, c, ai, bi, ci);
        size_t o = ((size_t)(p * NCH + ch) * 3) * NS + tid;
        g_colp[o + 0 * NS] = mk_key(a, ai);
        g_colp[o + 1 * NS] = mk_key(b, bi);
        g_colp[o + 2 * NS] = mk_key(c, ci);
    }
}

// ---- K2: finalize col top-3 (reduce 8 partials) + convert row/col triples
//      to (idx, 0.5*exp(val)). One block per p. ----
__global__ __launch_bounds__(256) void k_reduce() {
    const int p = blockIdx.x, t = threadIdx.x;

    // Column reduce: thread = column t (coalesced u64 loads).
    {
        const unsigned long long* base = g_colp + (size_t)p * NCH * 3 * NS + t;
        unsigned long long a = 0ULL, b = 0ULL, c = 0ULL;
        #pragma unroll
        for (int ch = 0; ch < NCH; ++ch) {
            ins3(base[(ch * 3 + 0) * NS], a, b, c);
            ins3(base[(ch * 3 + 1) * NS], a, b, c);
            ins3(base[(ch * 3 + 2) * NS], a, b, c);
        }
        size_t o = (size_t)p * 3 * NS + t;
        g_cidx[o + 0 * NS] = key_idx(a);  g_cval[o + 0 * NS] = 0.5f * expf(key_val(a));
        g_cidx[o + 1 * NS] = key_idx(b);  g_cval[o + 1 * NS] = 0.5f * expf(key_val(b));
        g_cidx[o + 2 * NS] = key_idx(c);  g_cval[o + 2 * NS] = 0.5f * expf(key_val(c));
    }
    // Row convert: thread = row t.
    {
        size_t o = ((size_t)p * NR + t) * 3;
        #pragma unroll
        for (int k = 0; k < 3; ++k) {
            unsigned long long kk = g_rowk[o + k];
            g_ridx[o + k] = key_idx(kk);
            g_rval[o + k] = 0.5f * expf(key_val(kk));
        }
    }
}

// ---- K3: fully-coalesced output fill (replaces memset + both scatters).
//      Block = (p, chunk of 32 rows); thread = column s. ----
__global__ __launch_bounds__(256) void k_fill(
    const int* __restrict__ ref_mask, const int* __restrict__ src_mask,
    float* __restrict__ out_score, float* __restrict__ out_corr)
{
    __shared__ int   rid[CHUNK][3];
    __shared__ float rv[CHUNK][3];
    __shared__ unsigned char rm[CHUNK];

    const int tid = threadIdx.x;
    const int p  = blockIdx.x >> 3;
    const int ch = blockIdx.x & 7;
    const int r0 = ch * CHUNK;

    if (tid < CHUNK * 3) {
        int rr = tid / 3, k = tid % 3;
        size_t o = ((size_t)p * NR + r0 + rr) * 3 + k;
        rid[rr][k] = g_ridx[o];
        rv[rr][k]  = g_rval[o];
    }
    if (tid < CHUNK) rm[tid] = (ref_mask[p * NR + r0 + tid] != 0) ? 1 : 0;

    size_t co = (size_t)p * 3 * NS + tid;
    const int   c0 = g_cidx[co + 0 * NS], c1 = g_cidx[co + 1 * NS], c2 = g_cidx[co + 2 * NS];
    const float w0 = g_cval[co + 0 * NS], w1 = g_cval[co + 1 * NS], w2 = g_cval[co + 2 * NS];
    const bool  ms = src_mask[p * NS + tid] != 0;
    __syncthreads();

    float* os = out_score + ((size_t)p * NR + r0) * NS + tid;
    float* oc = out_corr  + ((size_t)p * NR + r0) * NS + tid;

    #pragma unroll 8
    for (int rr = 0; rr < CHUNK; ++rr) {
        const int r = r0 + rr;
        float v = (tid == rid[rr][0]) ? rv[rr][0]
                : (tid == rid[rr][1]) ? rv[rr][1]
                : (tid == rid[rr][2]) ? rv[rr][2] : 0.0f;
        float w = (r == c0) ? w0 : (r == c1) ? w1 : (r == c2) ? w2 : 0.0f;
        float sc = v + w;                       // halves pre-scaled by 0.5
        bool corr = rm[rr] && ms && (sc > 0.0f);  // exp>0 iff selected (incl. underflow)
        os[rr * NS] = sc;
        oc[rr * NS] = corr ? 1.0f : 0.0f;
    }
}

extern "C" void kernel_launch(void* const* d_in, const int* in_sizes, int n_in,
                              void* d_out, int out_size) {
    // inputs: matching_score_map [P,R,S] f32, node_corr_scores [P] f32 (unused),
    //         ref_knn_masks [P,R] bool(4B words), src_knn_masks [P,S] bool(4B words)
    const float* score = (const float*)d_in[0];
    const int*   refm  = (const int*)d_in[2];
    const int*   srcm  = (const int*)d_in[3];

    float* out = (float*)d_out;
    size_t total = (size_t)NP * NR * NS;
    float* out_corr = out + total;    // [score_map f32 | corr_map bool->f32]

    k_top<<<NP * NCH, 256>>>(score);
    k_reduce<<<NP, 256>>>();
    k_fill<<<NP * NCH, 256>>>(refm, srcm, out, out_corr);
}